// round 6
// baseline (speedup 1.0000x reference)
#include <cuda_runtime.h>
#include <cstdint>

// GrokkingSNN: B=32768, hidden=512, p=97, 15 steps.
//   cur1[b,j] = P1[x0,j] + P2[x1,j] + b1[j], P = E @ W1half.T  (97x512 each)
//   9409 distinct (x0,x1) pairs -> simulate per pair.
//   mem2 = (sum_t beta2^{15-t} spk_t) @ W2.T + b2 * G; scatter to 32768 rows.
// R6: precompute re-gridded (416 blocks, 3 CTA/SM); phase-1 recurrence fused
//     to 3 fma-class ops/step; phase-2 W2 double-buffered (KC=32).

#define HIDDEN 512
#define PDIM 97
#define NPAIR (PDIM * PDIM)   // 9409
#define NSTEPS 15
#define UPITCH 104

#define SPITCH 68   // Ssm pitch (floats)
#define WP2 34      // packed W2 pitch (8B words), even -> 16B-aligned k-pairs
#define KC 32       // K-chunk for W2 staging (double-buffered)

// precompute tiling
#define PJT 32      // j per block
#define PVT 8       // v per block
#define W1P4 33     // W1 chunk pitch in float4 (odd -> conflict-free LDS.128)

__device__ float g_P[2 * PDIM * HIDDEN];    // [s][v][j]
__device__ float g_U[NPAIR * UPITCH];       // per-pair output rows (+bias)

typedef unsigned long long ull;

__device__ __forceinline__ void ffma2(ull& d, ull a, ull b) {
    asm("fma.rn.f32x2 %0, %1, %2, %0;" : "+l"(d) : "l"(a), "l"(b));
}
__device__ __forceinline__ ull fma2v(ull a, ull b, ull c) {
    ull d; asm("fma.rn.f32x2 %0, %1, %2, %3;" : "=l"(d) : "l"(a), "l"(b), "l"(c));
    return d;
}
__device__ __forceinline__ ull add2(ull a, ull b) {
    ull d; asm("add.rn.f32x2 %0, %1, %2;" : "=l"(d) : "l"(a), "l"(b));
    return d;
}
__device__ __forceinline__ ull pack2(float lo, float hi) {
    ull u; asm("mov.b64 %0, {%1, %2};" : "=l"(u) : "f"(lo), "f"(hi));
    return u;
}
__device__ __forceinline__ ull dup_f32(float w) {
    ull u; asm("mov.b64 %0, {%1, %1};" : "=l"(u) : "f"(w));
    return u;
}
__device__ __forceinline__ void unpack2(ull v, float& lo, float& hi) {
    asm("mov.b64 {%0, %1}, %2;" : "=f"(lo), "=f"(hi) : "l"(v));
}
__device__ __forceinline__ float fsetgt(float a, float b) {
    float d; asm("set.gt.f32.f32 %0, %1, %2;" : "=f"(d) : "f"(a), "f"(b));
    return d;   // 1.0f if a>b else 0.0f
}

// ---------------------------------------------------------------------------
// Kernel A: P[s][v][j] = sum_k E[v][k] * W1[j][s*512+k]
// grid (16 jt of 32 j, 13 vt of 8 v, 2 s) = 416 blocks, 128 threads.
// ~3 CTAs/SM. E tile staged once (warp-broadcast reads); W1 chunks
// register-double-buffered. k-ascending accumulation chains (unchanged).
// ---------------------------------------------------------------------------
__global__ void __launch_bounds__(128) precompute_kernel(
    const float* __restrict__ E, const float* __restrict__ W1)
{
    extern __shared__ float4 psm[];
    float4* Es4  = psm;                        // [PVT][128]
    float4* W1s4 = psm + PVT * (HIDDEN / 4);   // [PJT][W1P4]

    const int jt = blockIdx.x, vt = blockIdx.y, s = blockIdx.z;
    const int tid  = threadIdx.x;
    const int lane = tid & 31;    // j within tile
    const int grp  = tid >> 5;    // 0..3 -> 2 v rows each (== warp id: broadcast)
    const int vbase = vt * PVT;

    // stage E tile (coalesced, zero-fill past row 96)
    const float4* E4 = reinterpret_cast<const float4*>(E);
    const float4 z4 = make_float4(0.f, 0.f, 0.f, 0.f);
#pragma unroll
    for (int r = 0; r < PVT * (HIDDEN / 4) / 128; r++) {
        int idx = tid + 128 * r;
        int vv = idx >> 7;
        int c4 = idx & 127;
        int v  = vbase + vv;
        Es4[vv * 128 + c4] = (v < PDIM) ? __ldg(E4 + v * 128 + c4) : z4;
    }

    // W1 row stride = 256 float4; chunk = [32 j][32 float4], 8 f4 per thread
    const float4* W14 = reinterpret_cast<const float4*>(W1);
    const int srow = tid >> 5;   // rows srow + 4*i
    const int sc4  = tid & 31;

    float4 r[8];
#pragma unroll
    for (int i = 0; i < 8; i++)
        r[i] = __ldg(W14 + (size_t)(jt * PJT + srow + 4 * i) * 256 + s * 128 + sc4);

    float acc0 = 0.f, acc1 = 0.f;

    for (int kb = 0; kb < 4; kb++) {
#pragma unroll
        for (int i = 0; i < 8; i++)
            W1s4[(srow + 4 * i) * W1P4 + sc4] = r[i];
        __syncthreads();
        if (kb < 3) {
#pragma unroll
            for (int i = 0; i < 8; i++)
                r[i] = __ldg(W14 + (size_t)(jt * PJT + srow + 4 * i) * 256
                             + s * 128 + (kb + 1) * 32 + sc4);
        }

#pragma unroll 8
        for (int k4 = 0; k4 < 32; k4++) {
            float4 w  = W1s4[lane * W1P4 + k4];
            float4 e0 = Es4[(grp * 2 + 0) * 128 + kb * 32 + k4];
            float4 e1 = Es4[(grp * 2 + 1) * 128 + kb * 32 + k4];
            acc0 = fmaf(e0.x, w.x, acc0);
            acc0 = fmaf(e0.y, w.y, acc0);
            acc0 = fmaf(e0.z, w.z, acc0);
            acc0 = fmaf(e0.w, w.w, acc0);
            acc1 = fmaf(e1.x, w.x, acc1);
            acc1 = fmaf(e1.y, w.y, acc1);
            acc1 = fmaf(e1.z, w.z, acc1);
            acc1 = fmaf(e1.w, w.w, acc1);
        }
        __syncthreads();
    }

    const int j = jt * PJT + lane;
    const int vg = vbase + grp * 2;
    if (vg < PDIM)     g_P[(s * PDIM + vg)     * HIDDEN + j] = acc0;
    if (vg + 1 < PDIM) g_P[(s * PDIM + vg + 1) * HIDDEN + j] = acc1;
}

// ---------------------------------------------------------------------------
// Kernel B: per-pair LIF sim -> weighted spike sums S (smem), then
// U = S @ W2.T + b2*G. 148 blocks x 64 pairs, 256 threads.
// Phase-1 recurrence: mm = fma(beta1, m, c); mm = fma(sp, -thr1, mm) — 3 ops.
// Phase-2: double-buffered W2 chunks (KC=32), k-paired LDS.128, FFMA2.
// ---------------------------------------------------------------------------
__global__ void __launch_bounds__(256, 1) pair_kernel(
    const float* __restrict__ b1, const float* __restrict__ W2,
    const float* __restrict__ b2, const float* __restrict__ pbeta1,
    const float* __restrict__ pbeta2, const float* __restrict__ pthr1)
{
    extern __shared__ float sm[];
    float* Ssm = sm;                                       // [512][SPITCH]
    ull* W2s = reinterpret_cast<ull*>(sm + 512 * SPITCH);  // [2][112][WP2]

    const float beta1 = fminf(fmaxf(__ldg(pbeta1), 0.1f), 0.9f);
    const float beta2 = fminf(fmaxf(__ldg(pbeta2), 0.1f), 0.9f);
    const float thr1  = fmaxf(__ldg(pthr1), 0.1f);

    const int tid = threadIdx.x;

    // prefetch W2 chunk 0 into buffer 0 (overlaps with phase 1)
    for (int idx = tid; idx < PDIM * KC; idx += 256) {
        int p = idx >> 5;
        int k = idx & 31;
        W2s[p * WP2 + k] = dup_f32(__ldg(W2 + p * HIDDEN + k));
    }

    // ---------------- phase 1: simulate 64 pairs x 512 h --------------------
    {
        const int q   = tid >> 2;   // pair slot 0..63
        const int sub = tid & 3;    // h-quarter
        int pp = blockIdx.x * 64 + q;
        if (pp >= NPAIR) pp = 0;    // junk lanes; phase-2 store is guarded
        const int a = pp / PDIM;
        const int b = pp - a * PDIM;
        const float4* p1  = reinterpret_cast<const float4*>(g_P + a * HIDDEN);
        const float4* p2  = reinterpret_cast<const float4*>(g_P + (PDIM + b) * HIDDEN);
        const float4* b14 = reinterpret_cast<const float4*>(b1);

        const ull bt1 = dup_f32(beta1);
        const ull bt2 = dup_f32(beta2);
        const ull nt2 = dup_f32(-thr1);

        float4 n1 = __ldg(p1 + sub), n2 = __ldg(p2 + sub), nb = __ldg(b14 + sub);

#pragma unroll 1
        for (int o = 0; o < 32; o++) {
            const float4 v1 = n1, v2 = n2, vb = nb;
            if (o < 31) {
                const int h4n = sub + 4 * (o + 1);
                n1 = __ldg(p1 + h4n);
                n2 = __ldg(p2 + h4n);
                nb = __ldg(b14 + h4n);
            }
            // c = (p1 + p2) + b1  (packed, same order/rounding as before)
            ull c01 = add2(add2(pack2(v1.x, v1.y), pack2(v2.x, v2.y)),
                           pack2(vb.x, vb.y));
            ull c23 = add2(add2(pack2(v1.z, v1.w), pack2(v2.z, v2.w)),
                           pack2(vb.z, vb.w));

            ull m01 = 0, m23 = 0, S01 = 0, S23 = 0, sp01 = 0, sp23 = 0;
#pragma unroll
            for (int t = 0; t < NSTEPS; t++) {
                // mm = fma(beta1, m, c) - sp*thr1  (fused: 3 fma-class ops)
                m01 = fma2v(sp01, nt2, fma2v(bt1, m01, c01));
                m23 = fma2v(sp23, nt2, fma2v(bt1, m23, c23));
                float a0, a1, a2, a3;
                unpack2(m01, a0, a1);
                unpack2(m23, a2, a3);
                sp01 = pack2(fsetgt(a0, thr1), fsetgt(a1, thr1));
                sp23 = pack2(fsetgt(a2, thr1), fsetgt(a3, thr1));
                S01 = fma2v(bt2, S01, sp01);
                S23 = fma2v(bt2, S23, sp23);
            }
            float s0, s1, s2, s3;
            unpack2(S01, s0, s1);
            unpack2(S23, s2, s3);
            const int h = (sub + 4 * o) * 4;
            Ssm[(h + 0) * SPITCH + q] = s0;
            Ssm[(h + 1) * SPITCH + q] = s1;
            Ssm[(h + 2) * SPITCH + q] = s2;
            Ssm[(h + 3) * SPITCH + q] = s3;
        }
    }
    __syncthreads();   // Ssm + W2 chunk 0 ready

    // ---------------- phase 2: U = S @ W2.T (double-buffered) ---------------
    const int tx = tid & 15;   // 4-pair group
    const int ty = tid >> 4;   // 7-p group

    ull acc01[7], acc23[7];
#pragma unroll
    for (int i = 0; i < 7; i++) { acc01[i] = 0ull; acc23[i] = 0ull; }

    for (int kb = 0; kb < HIDDEN / KC; kb++) {
        const ull* Wb = W2s + (kb & 1) * 112 * WP2;
        if (kb < HIDDEN / KC - 1) {
            ull* Wn = W2s + ((kb + 1) & 1) * 112 * WP2;
            for (int idx = tid; idx < PDIM * KC; idx += 256) {
                int p = idx >> 5;
                int k = idx & 31;
                Wn[p * WP2 + k] =
                    dup_f32(__ldg(W2 + p * HIDDEN + (kb + 1) * KC + k));
            }
        }

#pragma unroll 4
        for (int k2 = 0; k2 < KC / 2; k2++) {
            const int kg = kb * KC + 2 * k2;
            ulonglong2 svA = *reinterpret_cast<const ulonglong2*>(
                Ssm + kg * SPITCH + tx * 4);
            ulonglong2 svB = *reinterpret_cast<const ulonglong2*>(
                Ssm + (kg + 1) * SPITCH + tx * 4);
#pragma unroll
            for (int i = 0; i < 7; i++) {
                ulonglong2 w = *reinterpret_cast<const ulonglong2*>(
                    Wb + (ty * 7 + i) * WP2 + 2 * k2);
                ffma2(acc01[i], svA.x, w.x);   // k   (ascending order kept)
                ffma2(acc23[i], svA.y, w.x);
                ffma2(acc01[i], svB.x, w.y);   // k+1
                ffma2(acc23[i], svB.y, w.y);
            }
        }
        __syncthreads();
    }

    // G = sum_{k=0..14} beta2^k via same recursion as mem2
    float G = 0.0f;
#pragma unroll
    for (int t = 0; t < NSTEPS; t++) G = __fadd_rn(__fmul_rn(beta2, G), 1.0f);

    const int ppb = blockIdx.x * 64 + tx * 4;
#pragma unroll
    for (int i = 0; i < 7; i++) {
        const int p = ty * 7 + i;
        if (p >= PDIM) break;
        const float bg = __ldg(b2 + p) * G;
        float f0, f1, f2, f3;
        unpack2(acc01[i], f0, f1);
        unpack2(acc23[i], f2, f3);
        float av[4] = {f0, f1, f2, f3};
#pragma unroll
        for (int jj = 0; jj < 4; jj++) {
            int pp = ppb + jj;
            if (pp < NPAIR) g_U[pp * UPITCH + p] = av[jj] + bg;
        }
    }
}

// ---------------------------------------------------------------------------
// Kernel C: out[b,:] = U[pair(b),:]. One warp per output row.
// ---------------------------------------------------------------------------
__global__ void __launch_bounds__(256) scatter_kernel(
    const int* __restrict__ x, float* __restrict__ out, int B)
{
    int warp = blockIdx.x * 8 + (threadIdx.x >> 5);
    int lane = threadIdx.x & 31;
    if (warp >= B) return;
    int x0 = __ldg(x + 2 * warp);
    int x1 = __ldg(x + 2 * warp + 1);
    const float* u = g_U + (size_t)(x0 * PDIM + x1) * UPITCH;
    float* o = out + (size_t)warp * PDIM;
#pragma unroll
    for (int j = 0; j < 3; j++) o[lane + 32 * j] = u[lane + 32 * j];
    if (lane == 0) o[96] = u[96];
}

// ---------------------------------------------------------------------------
extern "C" void kernel_launch(void* const* d_in, const int* in_sizes, int n_in,
                              void* d_out, int out_size)
{
    const int*   x     = (const int*)  d_in[0];
    const float* E     = (const float*)d_in[1];
    const float* W1    = (const float*)d_in[2];
    const float* b1    = (const float*)d_in[3];
    const float* W2    = (const float*)d_in[4];
    const float* b2    = (const float*)d_in[5];
    const float* beta1 = (const float*)d_in[6];
    const float* beta2 = (const float*)d_in[7];
    const float* thr1  = (const float*)d_in[8];
    // thr2 unused in forward (lif2 reset='none'; output is mem2).

    const int B = in_sizes[0] / 2;

    const int psmemB = (PVT * (HIDDEN / 4) + PJT * W1P4) * (int)sizeof(float4); // 33280
    cudaFuncSetAttribute(precompute_kernel,
                         cudaFuncAttributeMaxDynamicSharedMemorySize, psmemB);

    const int smemB = 512 * SPITCH * (int)sizeof(float)
                    + 2 * 112 * WP2 * (int)sizeof(ull); // 200192
    cudaFuncSetAttribute(pair_kernel, cudaFuncAttributeMaxDynamicSharedMemorySize, smemB);

    precompute_kernel<<<dim3(16, 13, 2), 128, psmemB>>>(E, W1);
    pair_kernel<<<148, 256, smemB>>>(b1, W2, b2, beta1, beta2, thr1);
    scatter_kernel<<<(B + 7) / 8, 256>>>(x, (float*)d_out, B);
}

// round 7
// speedup vs baseline: 1.1565x; 1.1565x over previous
#include <cuda_runtime.h>
#include <cstdint>

// GrokkingSNN: B=32768, hidden=512, p=97, 15 steps.
//   cur1[b,j] = P1[x0,j] + P2[x1,j] + b1[j], P = E @ W1half.T
//   9409 distinct pairs -> simulate per pair; mem2 = S @ W2.T + b2*G.
// R7: phase-2 GEMM on tensor cores via 3xTF32-split mma.sync (m16n8k8).
//     Phase-1 LIF recurrence unchanged (bit-identical to R6).

#define HIDDEN 512
#define PDIM 97
#define NPAIR (PDIM * PDIM)   // 9409
#define NSTEPS 15
#define UPITCH 104

#define SPITCH 516  // Ssm pair-major pitch (floats); 516 mod 32 = 4 -> A frags conflict-free
#define WPIT 68     // W2 tf32 tile pitch; 68 mod 32 = 4 -> B frags conflict-free
#define KCH 64      // K-chunk for W2 staging

// precompute tiling (unchanged from R6)
#define PJT 32
#define PVT 8
#define W1P4 33

__device__ float g_P[2 * PDIM * HIDDEN];
__device__ float g_U[NPAIR * UPITCH];

typedef unsigned long long ull;
typedef unsigned int u32;

__device__ __forceinline__ ull fma2v(ull a, ull b, ull c) {
    ull d; asm("fma.rn.f32x2 %0, %1, %2, %3;" : "=l"(d) : "l"(a), "l"(b), "l"(c));
    return d;
}
__device__ __forceinline__ ull add2(ull a, ull b) {
    ull d; asm("add.rn.f32x2 %0, %1, %2;" : "=l"(d) : "l"(a), "l"(b));
    return d;
}
__device__ __forceinline__ ull pack2(float lo, float hi) {
    ull u; asm("mov.b64 %0, {%1, %2};" : "=l"(u) : "f"(lo), "f"(hi));
    return u;
}
__device__ __forceinline__ ull dup_f32(float w) {
    ull u; asm("mov.b64 %0, {%1, %1};" : "=l"(u) : "f"(w));
    return u;
}
__device__ __forceinline__ void unpack2(ull v, float& lo, float& hi) {
    asm("mov.b64 {%0, %1}, %2;" : "=f"(lo), "=f"(hi) : "l"(v));
}
__device__ __forceinline__ float fsetgt(float a, float b) {
    float d; asm("set.gt.f32.f32 %0, %1, %2;" : "=f"(d) : "f"(a), "f"(b));
    return d;
}
__device__ __forceinline__ u32 f2tf32(float f) {
    u32 u; asm("cvt.rna.tf32.f32 %0, %1;" : "=r"(u) : "f"(f));
    return u;
}
__device__ __forceinline__ void mma_tf32(float* c, const u32* a, u32 b0, u32 b1) {
    asm("mma.sync.aligned.m16n8k8.row.col.f32.tf32.tf32.f32 "
        "{%0,%1,%2,%3}, {%4,%5,%6,%7}, {%8,%9}, {%0,%1,%2,%3};"
        : "+f"(c[0]), "+f"(c[1]), "+f"(c[2]), "+f"(c[3])
        : "r"(a[0]), "r"(a[1]), "r"(a[2]), "r"(a[3]), "r"(b0), "r"(b1));
}

// ---------------------------------------------------------------------------
// Kernel A: P[s][v][j] = sum_k E[v][k] * W1[j][s*512+k]   (unchanged from R6)
// ---------------------------------------------------------------------------
__global__ void __launch_bounds__(128) precompute_kernel(
    const float* __restrict__ E, const float* __restrict__ W1)
{
    extern __shared__ float4 psm[];
    float4* Es4  = psm;                        // [PVT][128]
    float4* W1s4 = psm + PVT * (HIDDEN / 4);   // [PJT][W1P4]

    const int jt = blockIdx.x, vt = blockIdx.y, s = blockIdx.z;
    const int tid  = threadIdx.x;
    const int lane = tid & 31;
    const int grp  = tid >> 5;
    const int vbase = vt * PVT;

    const float4* E4 = reinterpret_cast<const float4*>(E);
    const float4 z4 = make_float4(0.f, 0.f, 0.f, 0.f);
#pragma unroll
    for (int r = 0; r < PVT * (HIDDEN / 4) / 128; r++) {
        int idx = tid + 128 * r;
        int vv = idx >> 7;
        int c4 = idx & 127;
        int v  = vbase + vv;
        Es4[vv * 128 + c4] = (v < PDIM) ? __ldg(E4 + v * 128 + c4) : z4;
    }

    const float4* W14 = reinterpret_cast<const float4*>(W1);
    const int srow = tid >> 5;
    const int sc4  = tid & 31;

    float4 r[8];
#pragma unroll
    for (int i = 0; i < 8; i++)
        r[i] = __ldg(W14 + (size_t)(jt * PJT + srow + 4 * i) * 256 + s * 128 + sc4);

    float acc0 = 0.f, acc1 = 0.f;

    for (int kb = 0; kb < 4; kb++) {
#pragma unroll
        for (int i = 0; i < 8; i++)
            W1s4[(srow + 4 * i) * W1P4 + sc4] = r[i];
        __syncthreads();
        if (kb < 3) {
#pragma unroll
            for (int i = 0; i < 8; i++)
                r[i] = __ldg(W14 + (size_t)(jt * PJT + srow + 4 * i) * 256
                             + s * 128 + (kb + 1) * 32 + sc4);
        }

#pragma unroll 8
        for (int k4 = 0; k4 < 32; k4++) {
            float4 w  = W1s4[lane * W1P4 + k4];
            float4 e0 = Es4[(grp * 2 + 0) * 128 + kb * 32 + k4];
            float4 e1 = Es4[(grp * 2 + 1) * 128 + kb * 32 + k4];
            acc0 = fmaf(e0.x, w.x, acc0);
            acc0 = fmaf(e0.y, w.y, acc0);
            acc0 = fmaf(e0.z, w.z, acc0);
            acc0 = fmaf(e0.w, w.w, acc0);
            acc1 = fmaf(e1.x, w.x, acc1);
            acc1 = fmaf(e1.y, w.y, acc1);
            acc1 = fmaf(e1.z, w.z, acc1);
            acc1 = fmaf(e1.w, w.w, acc1);
        }
        __syncthreads();
    }

    const int j = jt * PJT + lane;
    const int vg = vbase + grp * 2;
    if (vg < PDIM)     g_P[(s * PDIM + vg)     * HIDDEN + j] = acc0;
    if (vg + 1 < PDIM) g_P[(s * PDIM + vg + 1) * HIDDEN + j] = acc1;
}

// ---------------------------------------------------------------------------
// Kernel B: phase 1 LIF sim (as R6) -> S pair-major in smem;
// phase 2: U = S @ W2.T via 3xTF32-split mma.sync. 148 blocks, 256 threads.
// ---------------------------------------------------------------------------
__global__ void __launch_bounds__(256, 1) pair_kernel(
    const float* __restrict__ b1, const float* __restrict__ W2,
    const float* __restrict__ b2, const float* __restrict__ pbeta1,
    const float* __restrict__ pbeta2, const float* __restrict__ pthr1)
{
    extern __shared__ float sm[];
    float* Ssm = sm;                                    // [64][SPITCH] fp32, pair-major
    u32* Wh = reinterpret_cast<u32*>(sm + 64 * SPITCH); // [104][WPIT] tf32 hi
    u32* Wl = Wh + 104 * WPIT;                          // [104][WPIT] tf32 lo

    const float beta1 = fminf(fmaxf(__ldg(pbeta1), 0.1f), 0.9f);
    const float beta2 = fminf(fmaxf(__ldg(pbeta2), 0.1f), 0.9f);
    const float thr1  = fmaxf(__ldg(pthr1), 0.1f);

    const int tid = threadIdx.x;

    // ---------------- phase 1: simulate 64 pairs x 512 h (R6 numerics) ------
    {
        const int q   = tid >> 2;   // pair slot 0..63
        const int sub = tid & 3;    // h-quarter
        int pp = blockIdx.x * 64 + q;
        if (pp >= NPAIR) pp = 0;
        const int a = pp / PDIM;
        const int b = pp - a * PDIM;
        const float4* p1  = reinterpret_cast<const float4*>(g_P + a * HIDDEN);
        const float4* p2  = reinterpret_cast<const float4*>(g_P + (PDIM + b) * HIDDEN);
        const float4* b14 = reinterpret_cast<const float4*>(b1);

        const ull bt1 = dup_f32(beta1);
        const ull bt2 = dup_f32(beta2);
        const ull nt2 = dup_f32(-thr1);

        float4 n1 = __ldg(p1 + sub), n2 = __ldg(p2 + sub), nb = __ldg(b14 + sub);

#pragma unroll 1
        for (int o = 0; o < 32; o++) {
            const float4 v1 = n1, v2 = n2, vb = nb;
            if (o < 31) {
                const int h4n = sub + 4 * (o + 1);
                n1 = __ldg(p1 + h4n);
                n2 = __ldg(p2 + h4n);
                nb = __ldg(b14 + h4n);
            }
            ull c01 = add2(add2(pack2(v1.x, v1.y), pack2(v2.x, v2.y)),
                           pack2(vb.x, vb.y));
            ull c23 = add2(add2(pack2(v1.z, v1.w), pack2(v2.z, v2.w)),
                           pack2(vb.z, vb.w));

            ull m01 = 0, m23 = 0, S01 = 0, S23 = 0, sp01 = 0, sp23 = 0;
#pragma unroll
            for (int t = 0; t < NSTEPS; t++) {
                m01 = fma2v(sp01, nt2, fma2v(bt1, m01, c01));
                m23 = fma2v(sp23, nt2, fma2v(bt1, m23, c23));
                float a0, a1, a2, a3;
                unpack2(m01, a0, a1);
                unpack2(m23, a2, a3);
                sp01 = pack2(fsetgt(a0, thr1), fsetgt(a1, thr1));
                sp23 = pack2(fsetgt(a2, thr1), fsetgt(a3, thr1));
                S01 = fma2v(bt2, S01, sp01);
                S23 = fma2v(bt2, S23, sp23);
            }
            float s0, s1, s2, s3;
            unpack2(S01, s0, s1);
            unpack2(S23, s2, s3);
            // pair-major store: Ssm[q][h..h+3], one STS.128
            const int h4 = sub + 4 * o;
            *reinterpret_cast<float4*>(Ssm + q * SPITCH + h4 * 4) =
                make_float4(s0, s1, s2, s3);
        }
    }
    __syncthreads();   // Ssm complete

    // ---------------- phase 2: tensor GEMM (3xTF32 split) -------------------
    const int warp = tid >> 5;
    const int lane = tid & 31;
    const int wm = warp & 1;    // 2 m-groups x 2 m16-tiles
    const int wn = warp >> 1;   // 4 n-groups; n-tiles nt = wn + 4*j (nt < 13)
    const int g  = lane >> 2;   // 0..7
    const int t  = lane & 3;    // 0..3

    float acc[2][4][4];
#pragma unroll
    for (int mt = 0; mt < 2; mt++)
#pragma unroll
        for (int j = 0; j < 4; j++)
#pragma unroll
            for (int e = 0; e < 4; e++) acc[mt][j][e] = 0.f;

    for (int kb = 0; kb < HIDDEN / KCH; kb++) {
        // stage W2 chunk as tf32 hi/lo (rows >= 97 zero)
        for (int idx = tid; idx < 104 * KCH; idx += 256) {
            int p = idx >> 6;
            int k = idx & (KCH - 1);
            float w = (p < PDIM) ? __ldg(W2 + p * HIDDEN + kb * KCH + k) : 0.f;
            u32 wh = f2tf32(w);
            u32 wl = f2tf32(w - __uint_as_float(wh));
            Wh[p * WPIT + k] = wh;
            Wl[p * WPIT + k] = wl;
        }
        __syncthreads();

#pragma unroll
        for (int ks = 0; ks < KCH / 8; ks++) {
            const int kg = kb * KCH + ks * 8;
            // A fragments (2 m-tiles), hi/lo split
            u32 ah[2][4], al[2][4];
#pragma unroll
            for (int mt = 0; mt < 2; mt++) {
                const int prow = (wm * 2 + mt) * 16 + g;
                const int kcol = kg + t;
                float a0 = Ssm[prow * SPITCH + kcol];
                float a1 = Ssm[(prow + 8) * SPITCH + kcol];
                float a2 = Ssm[prow * SPITCH + kcol + 4];
                float a3 = Ssm[(prow + 8) * SPITCH + kcol + 4];
                ah[mt][0] = f2tf32(a0); al[mt][0] = f2tf32(a0 - __uint_as_float(ah[mt][0]));
                ah[mt][1] = f2tf32(a1); al[mt][1] = f2tf32(a1 - __uint_as_float(ah[mt][1]));
                ah[mt][2] = f2tf32(a2); al[mt][2] = f2tf32(a2 - __uint_as_float(ah[mt][2]));
                ah[mt][3] = f2tf32(a3); al[mt][3] = f2tf32(a3 - __uint_as_float(ah[mt][3]));
            }
#pragma unroll
            for (int j = 0; j < 4; j++) {
                const int nt = wn + 4 * j;
                if (nt < 13) {
                    const int nrow = nt * 8 + g;
                    const int kk = ks * 8 + t;
                    u32 bh0 = Wh[nrow * WPIT + kk];
                    u32 bh1 = Wh[nrow * WPIT + kk + 4];
                    u32 bl0 = Wl[nrow * WPIT + kk];
                    u32 bl1 = Wl[nrow * WPIT + kk + 4];
#pragma unroll
                    for (int mt = 0; mt < 2; mt++) {
                        mma_tf32(acc[mt][j], ah[mt], bh0, bh1);  // hi*hi
                        mma_tf32(acc[mt][j], al[mt], bh0, bh1);  // lo*hi
                        mma_tf32(acc[mt][j], ah[mt], bl0, bl1);  // hi*lo
                    }
                }
            }
        }
        __syncthreads();   // chunk consumed before restage
    }

    // G = sum_{k=0..14} beta2^k via same recursion as mem2
    float G = 0.0f;
#pragma unroll
    for (int t2 = 0; t2 < NSTEPS; t2++) G = __fadd_rn(__fmul_rn(beta2, G), 1.0f);

    // store: c0:(g,2t) c1:(g,2t+1) c2:(g+8,2t) c3:(g+8,2t+1)
#pragma unroll
    for (int mt = 0; mt < 2; mt++) {
#pragma unroll
        for (int j = 0; j < 4; j++) {
            const int nt = wn + 4 * j;
            if (nt < 13) {
#pragma unroll
                for (int e = 0; e < 4; e++) {
                    const int pp = blockIdx.x * 64 + (wm * 2 + mt) * 16 + g
                                 + (e >> 1) * 8;
                    const int n = nt * 8 + 2 * t + (e & 1);
                    if (pp < NPAIR && n < PDIM)
                        g_U[pp * UPITCH + n] = acc[mt][j][e] + __ldg(b2 + n) * G;
                }
            }
        }
    }
}

// ---------------------------------------------------------------------------
// Kernel C: out[b,:] = U[pair(b),:]. One warp per output row.
// ---------------------------------------------------------------------------
__global__ void __launch_bounds__(256) scatter_kernel(
    const int* __restrict__ x, float* __restrict__ out, int B)
{
    int warp = blockIdx.x * 8 + (threadIdx.x >> 5);
    int lane = threadIdx.x & 31;
    if (warp >= B) return;
    int x0 = __ldg(x + 2 * warp);
    int x1 = __ldg(x + 2 * warp + 1);
    const float* u = g_U + (size_t)(x0 * PDIM + x1) * UPITCH;
    float* o = out + (size_t)warp * PDIM;
#pragma unroll
    for (int j = 0; j < 3; j++) o[lane + 32 * j] = u[lane + 32 * j];
    if (lane == 0) o[96] = u[96];
}

// ---------------------------------------------------------------------------
extern "C" void kernel_launch(void* const* d_in, const int* in_sizes, int n_in,
                              void* d_out, int out_size)
{
    const int*   x     = (const int*)  d_in[0];
    const float* E     = (const float*)d_in[1];
    const float* W1    = (const float*)d_in[2];
    const float* b1    = (const float*)d_in[3];
    const float* W2    = (const float*)d_in[4];
    const float* b2    = (const float*)d_in[5];
    const float* beta1 = (const float*)d_in[6];
    const float* beta2 = (const float*)d_in[7];
    const float* thr1  = (const float*)d_in[8];
    // thr2 unused in forward (lif2 reset='none'; output is mem2).

    const int B = in_sizes[0] / 2;

    const int psmemB = (PVT * (HIDDEN / 4) + PJT * W1P4) * (int)sizeof(float4);
    cudaFuncSetAttribute(precompute_kernel,
                         cudaFuncAttributeMaxDynamicSharedMemorySize, psmemB);

    const int smemB = 64 * SPITCH * (int)sizeof(float)
                    + 2 * 104 * WPIT * (int)sizeof(u32);   // 188672 B
    cudaFuncSetAttribute(pair_kernel, cudaFuncAttributeMaxDynamicSharedMemorySize, smemB);

    precompute_kernel<<<dim3(16, 13, 2), 128, psmemB>>>(E, W1);
    pair_kernel<<<148, 256, smemB>>>(b1, W2, b2, beta1, beta2, thr1);
    scatter_kernel<<<(B + 7) / 8, 256>>>(x, (float*)d_out, B);
}

// round 8
// speedup vs baseline: 1.4702x; 1.2713x over previous
#include <cuda_runtime.h>
#include <cstdint>

// GrokkingSNN: B=32768, hidden=512, p=97, 15 steps.
//   cur1[b,j] = P1[x0,j] + P2[x1,j] + b1[j], P = E @ W1half.T
//   9409 distinct pairs -> simulate per pair; mem2 = S @ W2.T + b2*G.
// R8: phase-2 GEMM via 3xBF16-split mma.sync m16n8k16 (hi*hi+hi*lo+lo*hi).
//     S converted to bf16 hi/lo ONCE in phase 1; W2 chunks staged as bf16
//     hi/lo double-buffered. Phase-1 LIF recurrence bit-identical to R6/R7.

#define HIDDEN 512
#define PDIM 97
#define NPAIR (PDIM * PDIM)   // 9409
#define NSTEPS 15
#define UPITCH 104

#define SHP 260     // S bf16x2 pitch (u32/row): 256 k-pairs + pad (4g+t banks)
#define WHP 36      // W2 bf16x2 chunk pitch (u32/row): 32 k-pairs + pad
#define KCH 64      // K per W2 chunk
#define WCHUNK (104 * WHP)

// precompute tiling (unchanged from R6/R7)
#define PJT 32
#define PVT 8
#define W1P4 33

__device__ float g_P[2 * PDIM * HIDDEN];
__device__ float g_U[NPAIR * UPITCH];

typedef unsigned long long ull;
typedef unsigned int u32;

__device__ __forceinline__ ull fma2v(ull a, ull b, ull c) {
    ull d; asm("fma.rn.f32x2 %0, %1, %2, %3;" : "=l"(d) : "l"(a), "l"(b), "l"(c));
    return d;
}
__device__ __forceinline__ ull add2(ull a, ull b) {
    ull d; asm("add.rn.f32x2 %0, %1, %2;" : "=l"(d) : "l"(a), "l"(b));
    return d;
}
__device__ __forceinline__ ull pack2(float lo, float hi) {
    ull u; asm("mov.b64 %0, {%1, %2};" : "=l"(u) : "f"(lo), "f"(hi));
    return u;
}
__device__ __forceinline__ ull dup_f32(float w) {
    ull u; asm("mov.b64 %0, {%1, %1};" : "=l"(u) : "f"(w));
    return u;
}
__device__ __forceinline__ void unpack2(ull v, float& lo, float& hi) {
    asm("mov.b64 {%0, %1}, %2;" : "=f"(lo), "=f"(hi) : "l"(v));
}
__device__ __forceinline__ float fsetgt(float a, float b) {
    float d; asm("set.gt.f32.f32 %0, %1, %2;" : "=f"(d) : "f"(a), "f"(b));
    return d;
}
// pack {hi16(hif), lo16(lof)} — low half holds even-k element
__device__ __forceinline__ u32 bfpack(float hif, float lof) {
    u32 d; asm("cvt.rn.bf16x2.f32 %0, %1, %2;" : "=r"(d) : "f"(hif), "f"(lof));
    return d;
}
__device__ __forceinline__ float bflo(u32 d) { return __uint_as_float(d << 16); }
__device__ __forceinline__ float bfhi(u32 d) { return __uint_as_float(d & 0xFFFF0000u); }

__device__ __forceinline__ void mma_bf16(float* c, const u32* a, u32 b0, u32 b1) {
    asm("mma.sync.aligned.m16n8k16.row.col.f32.bf16.bf16.f32 "
        "{%0,%1,%2,%3}, {%4,%5,%6,%7}, {%8,%9}, {%0,%1,%2,%3};"
        : "+f"(c[0]), "+f"(c[1]), "+f"(c[2]), "+f"(c[3])
        : "r"(a[0]), "r"(a[1]), "r"(a[2]), "r"(a[3]), "r"(b0), "r"(b1));
}

// ---------------------------------------------------------------------------
// Kernel A: P[s][v][j] = sum_k E[v][k] * W1[j][s*512+k]   (unchanged)
// ---------------------------------------------------------------------------
__global__ void __launch_bounds__(128) precompute_kernel(
    const float* __restrict__ E, const float* __restrict__ W1)
{
    extern __shared__ float4 psm[];
    float4* Es4  = psm;                        // [PVT][128]
    float4* W1s4 = psm + PVT * (HIDDEN / 4);   // [PJT][W1P4]

    const int jt = blockIdx.x, vt = blockIdx.y, s = blockIdx.z;
    const int tid  = threadIdx.x;
    const int lane = tid & 31;
    const int grp  = tid >> 5;
    const int vbase = vt * PVT;

    const float4* E4 = reinterpret_cast<const float4*>(E);
    const float4 z4 = make_float4(0.f, 0.f, 0.f, 0.f);
#pragma unroll
    for (int r = 0; r < PVT * (HIDDEN / 4) / 128; r++) {
        int idx = tid + 128 * r;
        int vv = idx >> 7;
        int c4 = idx & 127;
        int v  = vbase + vv;
        Es4[vv * 128 + c4] = (v < PDIM) ? __ldg(E4 + v * 128 + c4) : z4;
    }

    const float4* W14 = reinterpret_cast<const float4*>(W1);
    const int srow = tid >> 5;
    const int sc4  = tid & 31;

    float4 r[8];
#pragma unroll
    for (int i = 0; i < 8; i++)
        r[i] = __ldg(W14 + (size_t)(jt * PJT + srow + 4 * i) * 256 + s * 128 + sc4);

    float acc0 = 0.f, acc1 = 0.f;

    for (int kb = 0; kb < 4; kb++) {
#pragma unroll
        for (int i = 0; i < 8; i++)
            W1s4[(srow + 4 * i) * W1P4 + sc4] = r[i];
        __syncthreads();
        if (kb < 3) {
#pragma unroll
            for (int i = 0; i < 8; i++)
                r[i] = __ldg(W14 + (size_t)(jt * PJT + srow + 4 * i) * 256
                             + s * 128 + (kb + 1) * 32 + sc4);
        }

#pragma unroll 8
        for (int k4 = 0; k4 < 32; k4++) {
            float4 w  = W1s4[lane * W1P4 + k4];
            float4 e0 = Es4[(grp * 2 + 0) * 128 + kb * 32 + k4];
            float4 e1 = Es4[(grp * 2 + 1) * 128 + kb * 32 + k4];
            acc0 = fmaf(e0.x, w.x, acc0);
            acc0 = fmaf(e0.y, w.y, acc0);
            acc0 = fmaf(e0.z, w.z, acc0);
            acc0 = fmaf(e0.w, w.w, acc0);
            acc1 = fmaf(e1.x, w.x, acc1);
            acc1 = fmaf(e1.y, w.y, acc1);
            acc1 = fmaf(e1.z, w.z, acc1);
            acc1 = fmaf(e1.w, w.w, acc1);
        }
        __syncthreads();
    }

    const int j = jt * PJT + lane;
    const int vg = vbase + grp * 2;
    if (vg < PDIM)     g_P[(s * PDIM + vg)     * HIDDEN + j] = acc0;
    if (vg + 1 < PDIM) g_P[(s * PDIM + vg + 1) * HIDDEN + j] = acc1;
}

// ---------------------------------------------------------------------------
// Kernel B: phase 1 LIF sim -> S as bf16 hi/lo (k-pair packed) in smem;
// phase 2: U = S @ W2.T via 3xBF16-split mma m16n8k16. 148 blocks, 256 thr.
// ---------------------------------------------------------------------------
__global__ void __launch_bounds__(256, 1) pair_kernel(
    const float* __restrict__ b1, const float* __restrict__ W2,
    const float* __restrict__ b2, const float* __restrict__ pbeta1,
    const float* __restrict__ pbeta2, const float* __restrict__ pthr1)
{
    extern __shared__ u32 smu[];
    u32* Sh = smu;                 // [64][SHP]
    u32* Sl = Sh + 64 * SHP;       // [64][SHP]
    u32* Wbuf = Sl + 64 * SHP;     // [2][2][104][WHP]  (buf, hi/lo)

    const float beta1 = fminf(fmaxf(__ldg(pbeta1), 0.1f), 0.9f);
    const float beta2 = fminf(fmaxf(__ldg(pbeta2), 0.1f), 0.9f);
    const float thr1  = fmaxf(__ldg(pthr1), 0.1f);

    const int tid = threadIdx.x;

    // ---- W2 chunk staging (bf16 hi/lo, rows >= 97 zero) ----
    auto stage = [&](int kb, int buf) {
        u32* Wh = Wbuf + buf * 2 * WCHUNK;
        u32* Wl = Wh + WCHUNK;
        for (int idx = tid; idx < 104 * (KCH / 2); idx += 256) {
            int p  = idx >> 5;          // 0..103
            int kp = idx & 31;          // k-pair within chunk
            float2 w = make_float2(0.f, 0.f);
            if (p < PDIM)
                w = *reinterpret_cast<const float2*>(
                        W2 + p * HIDDEN + kb * KCH + 2 * kp);
            u32 h = bfpack(w.y, w.x);
            u32 l = bfpack(w.y - bfhi(h), w.x - bflo(h));
            Wh[p * WHP + kp] = h;
            Wl[p * WHP + kp] = l;
        }
    };

    stage(0, 0);   // overlaps with phase 1 (separate smem region)

    // ---------------- phase 1: simulate 64 pairs x 512 h (R6 numerics) ------
    {
        const int q   = tid >> 2;   // pair slot 0..63
        const int sub = tid & 3;    // h-quarter
        int pp = blockIdx.x * 64 + q;
        if (pp >= NPAIR) pp = 0;
        const int a = pp / PDIM;
        const int b = pp - a * PDIM;
        const float4* p1  = reinterpret_cast<const float4*>(g_P + a * HIDDEN);
        const float4* p2  = reinterpret_cast<const float4*>(g_P + (PDIM + b) * HIDDEN);
        const float4* b14 = reinterpret_cast<const float4*>(b1);

        const ull bt1 = dup_f32(beta1);
        const ull bt2 = dup_f32(beta2);
        const ull nt2 = dup_f32(-thr1);

        float4 n1 = __ldg(p1 + sub), n2 = __ldg(p2 + sub), nb = __ldg(b14 + sub);

#pragma unroll 1
        for (int o = 0; o < 32; o++) {
            const float4 v1 = n1, v2 = n2, vb = nb;
            if (o < 31) {
                const int h4n = sub + 4 * (o + 1);
                n1 = __ldg(p1 + h4n);
                n2 = __ldg(p2 + h4n);
                nb = __ldg(b14 + h4n);
            }
            ull c01 = add2(add2(pack2(v1.x, v1.y), pack2(v2.x, v2.y)),
                           pack2(vb.x, vb.y));
            ull c23 = add2(add2(pack2(v1.z, v1.w), pack2(v2.z, v2.w)),
                           pack2(vb.z, vb.w));

            ull m01 = 0, m23 = 0, S01 = 0, S23 = 0, sp01 = 0, sp23 = 0;
#pragma unroll
            for (int t = 0; t < NSTEPS; t++) {
                m01 = fma2v(sp01, nt2, fma2v(bt1, m01, c01));
                m23 = fma2v(sp23, nt2, fma2v(bt1, m23, c23));
                float a0, a1, a2, a3;
                unpack2(m01, a0, a1);
                unpack2(m23, a2, a3);
                sp01 = pack2(fsetgt(a0, thr1), fsetgt(a1, thr1));
                sp23 = pack2(fsetgt(a2, thr1), fsetgt(a3, thr1));
                S01 = fma2v(bt2, S01, sp01);
                S23 = fma2v(bt2, S23, sp23);
            }
            float s0, s1, s2, s3;
            unpack2(S01, s0, s1);
            unpack2(S23, s2, s3);
            // bf16 hi/lo split, k-pair packed: cols 2*h4, 2*h4+1
            u32 h0 = bfpack(s1, s0);
            u32 l0 = bfpack(s1 - bfhi(h0), s0 - bflo(h0));
            u32 h1 = bfpack(s3, s2);
            u32 l1 = bfpack(s3 - bfhi(h1), s2 - bflo(h1));
            const int h4 = sub + 4 * o;
            *reinterpret_cast<ull*>(Sh + q * SHP + 2 * h4) =
                (ull)h0 | ((ull)h1 << 32);
            *reinterpret_cast<ull*>(Sl + q * SHP + 2 * h4) =
                (ull)l0 | ((ull)l1 << 32);
        }
    }
    __syncthreads();   // Sh/Sl complete + W2 chunk 0 staged

    // ---------------- phase 2: tensor GEMM (3xBF16 split) -------------------
    const int warp = tid >> 5;
    const int lane = tid & 31;
    const int wm = warp & 1;    // 2 m-groups x 2 m16-tiles
    const int wn = warp >> 1;   // 4 n-groups; n-tiles nt = wn + 4*j (nt < 13)
    const int g  = lane >> 2;
    const int t  = lane & 3;

    float acc[2][4][4];
#pragma unroll
    for (int mt = 0; mt < 2; mt++)
#pragma unroll
        for (int j = 0; j < 4; j++)
#pragma unroll
            for (int e = 0; e < 4; e++) acc[mt][j][e] = 0.f;

    for (int kb = 0; kb < HIDDEN / KCH; kb++) {
        if (kb < HIDDEN / KCH - 1) stage(kb + 1, (kb + 1) & 1);
        const u32* Wh = Wbuf + (kb & 1) * 2 * WCHUNK;
        const u32* Wl = Wh + WCHUNK;

#pragma unroll
        for (int ksl = 0; ksl < KCH / 16; ksl++) {
            const int kpg = (kb * (KCH / 16) + ksl) * 8 + t;  // global k-pair col
            const int kpl = ksl * 8 + t;                      // chunk-local col
            u32 ah[2][4], al[2][4];
#pragma unroll
            for (int mt = 0; mt < 2; mt++) {
                const int prow = (wm * 2 + mt) * 16 + g;
                ah[mt][0] = Sh[prow * SHP + kpg];
                ah[mt][1] = Sh[(prow + 8) * SHP + kpg];
                ah[mt][2] = Sh[prow * SHP + kpg + 4];
                ah[mt][3] = Sh[(prow + 8) * SHP + kpg + 4];
                al[mt][0] = Sl[prow * SHP + kpg];
                al[mt][1] = Sl[(prow + 8) * SHP + kpg];
                al[mt][2] = Sl[prow * SHP + kpg + 4];
                al[mt][3] = Sl[(prow + 8) * SHP + kpg + 4];
            }
#pragma unroll
            for (int j = 0; j < 4; j++) {
                const int nt = wn + 4 * j;
                if (nt < 13) {
                    const int nrow = nt * 8 + g;
                    u32 bh0 = Wh[nrow * WHP + kpl];
                    u32 bh1 = Wh[nrow * WHP + kpl + 4];
                    u32 bl0 = Wl[nrow * WHP + kpl];
                    u32 bl1 = Wl[nrow * WHP + kpl + 4];
#pragma unroll
                    for (int mt = 0; mt < 2; mt++) {
                        mma_bf16(acc[mt][j], ah[mt], bh0, bh1);  // hi*hi
                        mma_bf16(acc[mt][j], al[mt], bh0, bh1);  // lo*hi
                        mma_bf16(acc[mt][j], ah[mt], bl0, bl1);  // hi*lo
                    }
                }
            }
        }
        __syncthreads();   // staging of kb+1 done; chunk kb consumed
    }

    // G = sum_{k=0..14} beta2^k via same recursion as mem2
    float G = 0.0f;
#pragma unroll
    for (int t2 = 0; t2 < NSTEPS; t2++) G = __fadd_rn(__fmul_rn(beta2, G), 1.0f);

    // store: c0:(g,2t) c1:(g,2t+1) c2:(g+8,2t) c3:(g+8,2t+1)
#pragma unroll
    for (int mt = 0; mt < 2; mt++) {
#pragma unroll
        for (int j = 0; j < 4; j++) {
            const int nt = wn + 4 * j;
            if (nt < 13) {
#pragma unroll
                for (int e = 0; e < 4; e++) {
                    const int pp = blockIdx.x * 64 + (wm * 2 + mt) * 16 + g
                                 + (e >> 1) * 8;
                    const int n = nt * 8 + 2 * t + (e & 1);
                    if (pp < NPAIR && n < PDIM)
                        g_U[pp * UPITCH + n] = acc[mt][j][e] + __ldg(b2 + n) * G;
                }
            }
        }
    }
}

// ---------------------------------------------------------------------------
// Kernel C: out[b,:] = U[pair(b),:]. One warp per output row.
// ---------------------------------------------------------------------------
__global__ void __launch_bounds__(256) scatter_kernel(
    const int* __restrict__ x, float* __restrict__ out, int B)
{
    int warp = blockIdx.x * 8 + (threadIdx.x >> 5);
    int lane = threadIdx.x & 31;
    if (warp >= B) return;
    int x0 = __ldg(x + 2 * warp);
    int x1 = __ldg(x + 2 * warp + 1);
    const float* u = g_U + (size_t)(x0 * PDIM + x1) * UPITCH;
    float* o = out + (size_t)warp * PDIM;
#pragma unroll
    for (int j = 0; j < 3; j++) o[lane + 32 * j] = u[lane + 32 * j];
    if (lane == 0) o[96] = u[96];
}

// ---------------------------------------------------------------------------
extern "C" void kernel_launch(void* const* d_in, const int* in_sizes, int n_in,
                              void* d_out, int out_size)
{
    const int*   x     = (const int*)  d_in[0];
    const float* E     = (const float*)d_in[1];
    const float* W1    = (const float*)d_in[2];
    const float* b1    = (const float*)d_in[3];
    const float* W2    = (const float*)d_in[4];
    const float* b2    = (const float*)d_in[5];
    const float* beta1 = (const float*)d_in[6];
    const float* beta2 = (const float*)d_in[7];
    const float* thr1  = (const float*)d_in[8];
    // thr2 unused in forward (lif2 reset='none'; output is mem2).

    const int B = in_sizes[0] / 2;

    const int psmemB = (PVT * (HIDDEN / 4) + PJT * W1P4) * (int)sizeof(float4);
    cudaFuncSetAttribute(precompute_kernel,
                         cudaFuncAttributeMaxDynamicSharedMemorySize, psmemB);

    const int smemB = (2 * 64 * SHP + 4 * WCHUNK) * (int)sizeof(u32); // 193024 B
    cudaFuncSetAttribute(pair_kernel, cudaFuncAttributeMaxDynamicSharedMemorySize, smemB);

    precompute_kernel<<<dim3(16, 13, 2), 128, psmemB>>>(E, W1);
    pair_kernel<<<148, 256, smemB>>>(b1, W2, b2, beta1, beta2, thr1);
    scatter_kernel<<<(B + 7) / 8, 256>>>(x, (float*)d_out, B);
}

// round 9
// speedup vs baseline: 1.5104x; 1.0273x over previous
#include <cuda_runtime.h>
#include <cstdint>

// GrokkingSNN: B=32768, hidden=512, p=97, 15 steps.
//   cur1[b,j] = P1[x0,j] + P2[x1,j] + b1[j], P = E @ W1half.T
//   9409 distinct pairs -> simulate per pair; mem2 = S @ W2.T + b2*G.
// R9: precompute with 4-way split accumulators (breaks FMA chain, 6 CTA/SM);
//     pair kernel re-tiled to 296 CTAs x 32 pairs (2 CTA/SM) for latency
//     hiding; phase-1/phase-2 per-element numerics identical to R8.

#define HIDDEN 512
#define PDIM 97
#define NPAIR (PDIM * PDIM)   // 9409
#define NSTEPS 15
#define UPITCH 104

#define NP 32       // pairs per CTA
#define SHP 260     // S bf16x2 pitch (u32/row)
#define WHP 36      // W2 bf16x2 chunk pitch (u32/row)
#define KCH 64      // K per W2 chunk
#define WCHUNK (104 * WHP)

// precompute tiling
#define PJT 32
#define PVT 8
#define W1P4 33

__device__ float g_P[2 * PDIM * HIDDEN];
__device__ float g_U[NPAIR * UPITCH];

typedef unsigned long long ull;
typedef unsigned int u32;

__device__ __forceinline__ ull fma2v(ull a, ull b, ull c) {
    ull d; asm("fma.rn.f32x2 %0, %1, %2, %3;" : "=l"(d) : "l"(a), "l"(b), "l"(c));
    return d;
}
__device__ __forceinline__ ull add2(ull a, ull b) {
    ull d; asm("add.rn.f32x2 %0, %1, %2;" : "=l"(d) : "l"(a), "l"(b));
    return d;
}
__device__ __forceinline__ ull pack2(float lo, float hi) {
    ull u; asm("mov.b64 %0, {%1, %2};" : "=l"(u) : "f"(lo), "f"(hi));
    return u;
}
__device__ __forceinline__ ull dup_f32(float w) {
    ull u; asm("mov.b64 %0, {%1, %1};" : "=l"(u) : "f"(w));
    return u;
}
__device__ __forceinline__ void unpack2(ull v, float& lo, float& hi) {
    asm("mov.b64 {%0, %1}, %2;" : "=f"(lo), "=f"(hi) : "l"(v));
}
__device__ __forceinline__ float fsetgt(float a, float b) {
    float d; asm("set.gt.f32.f32 %0, %1, %2;" : "=f"(d) : "f"(a), "f"(b));
    return d;
}
__device__ __forceinline__ u32 bfpack(float hif, float lof) {
    u32 d; asm("cvt.rn.bf16x2.f32 %0, %1, %2;" : "=r"(d) : "f"(hif), "f"(lof));
    return d;
}
__device__ __forceinline__ float bflo(u32 d) { return __uint_as_float(d << 16); }
__device__ __forceinline__ float bfhi(u32 d) { return __uint_as_float(d & 0xFFFF0000u); }

__device__ __forceinline__ void mma_bf16(float* c, const u32* a, u32 b0, u32 b1) {
    asm("mma.sync.aligned.m16n8k16.row.col.f32.bf16.bf16.f32 "
        "{%0,%1,%2,%3}, {%4,%5,%6,%7}, {%8,%9}, {%0,%1,%2,%3};"
        : "+f"(c[0]), "+f"(c[1]), "+f"(c[2]), "+f"(c[3])
        : "r"(a[0]), "r"(a[1]), "r"(a[2]), "r"(a[3]), "r"(b0), "r"(b1));
}

// ---------------------------------------------------------------------------
// Kernel A: P[s][v][j] = sum_k E[v][k] * W1[j][s*512+k]
// 4-way split accumulators per v-row (pipelined chains), 6 CTAs/SM.
// ---------------------------------------------------------------------------
__global__ void __launch_bounds__(128) precompute_kernel(
    const float* __restrict__ E, const float* __restrict__ W1)
{
    extern __shared__ float4 psm[];
    float4* Es4  = psm;                        // [PVT][128]
    float4* W1s4 = psm + PVT * (HIDDEN / 4);   // [PJT][W1P4]

    const int jt = blockIdx.x, vt = blockIdx.y, s = blockIdx.z;
    const int tid  = threadIdx.x;
    const int lane = tid & 31;
    const int grp  = tid >> 5;
    const int vbase = vt * PVT;

    const float4* E4 = reinterpret_cast<const float4*>(E);
    const float4 z4 = make_float4(0.f, 0.f, 0.f, 0.f);
#pragma unroll
    for (int r = 0; r < PVT * (HIDDEN / 4) / 128; r++) {
        int idx = tid + 128 * r;
        int vv = idx >> 7;
        int c4 = idx & 127;
        int v  = vbase + vv;
        Es4[vv * 128 + c4] = (v < PDIM) ? __ldg(E4 + v * 128 + c4) : z4;
    }

    const float4* W14 = reinterpret_cast<const float4*>(W1);
    const int srow = tid >> 5;
    const int sc4  = tid & 31;

    float4 r[8];
#pragma unroll
    for (int i = 0; i < 8; i++)
        r[i] = __ldg(W14 + (size_t)(jt * PJT + srow + 4 * i) * 256 + s * 128 + sc4);

    float ac[2][4];
#pragma unroll
    for (int v = 0; v < 2; v++)
#pragma unroll
        for (int cix = 0; cix < 4; cix++) ac[v][cix] = 0.f;

    for (int kb = 0; kb < 4; kb++) {
#pragma unroll
        for (int i = 0; i < 8; i++)
            W1s4[(srow + 4 * i) * W1P4 + sc4] = r[i];
        __syncthreads();
        if (kb < 3) {
#pragma unroll
            for (int i = 0; i < 8; i++)
                r[i] = __ldg(W14 + (size_t)(jt * PJT + srow + 4 * i) * 256
                             + s * 128 + (kb + 1) * 32 + sc4);
        }

#pragma unroll 8
        for (int k4 = 0; k4 < 32; k4++) {
            float4 w  = W1s4[lane * W1P4 + k4];
            float4 e0 = Es4[(grp * 2 + 0) * 128 + kb * 32 + k4];
            float4 e1 = Es4[(grp * 2 + 1) * 128 + kb * 32 + k4];
            ac[0][0] = fmaf(e0.x, w.x, ac[0][0]);
            ac[0][1] = fmaf(e0.y, w.y, ac[0][1]);
            ac[0][2] = fmaf(e0.z, w.z, ac[0][2]);
            ac[0][3] = fmaf(e0.w, w.w, ac[0][3]);
            ac[1][0] = fmaf(e1.x, w.x, ac[1][0]);
            ac[1][1] = fmaf(e1.y, w.y, ac[1][1]);
            ac[1][2] = fmaf(e1.z, w.z, ac[1][2]);
            ac[1][3] = fmaf(e1.w, w.w, ac[1][3]);
        }
        __syncthreads();
    }

    const float acc0 = __fadd_rn(__fadd_rn(ac[0][0], ac[0][1]),
                                 __fadd_rn(ac[0][2], ac[0][3]));
    const float acc1 = __fadd_rn(__fadd_rn(ac[1][0], ac[1][1]),
                                 __fadd_rn(ac[1][2], ac[1][3]));

    const int j = jt * PJT + lane;
    const int vg = vbase + grp * 2;
    if (vg < PDIM)     g_P[(s * PDIM + vg)     * HIDDEN + j] = acc0;
    if (vg + 1 < PDIM) g_P[(s * PDIM + vg + 1) * HIDDEN + j] = acc1;
}

// ---------------------------------------------------------------------------
// Kernel B: 296 CTAs x 32 pairs, 256 threads, 2 CTAs/SM.
// Phase 1: LIF sim -> S bf16 hi/lo (k-pair packed) in smem (R8 numerics).
// Phase 2: U = S @ W2.T via 3xBF16-split mma m16n8k16, W2 single-buffered.
// ---------------------------------------------------------------------------
__global__ void __launch_bounds__(256, 2) pair_kernel(
    const float* __restrict__ b1, const float* __restrict__ W2,
    const float* __restrict__ b2, const float* __restrict__ pbeta1,
    const float* __restrict__ pbeta2, const float* __restrict__ pthr1)
{
    extern __shared__ u32 smu[];
    u32* Sh = smu;                 // [NP][SHP]
    u32* Sl = Sh + NP * SHP;       // [NP][SHP]
    u32* Wh = Sl + NP * SHP;       // [104][WHP]
    u32* Wl = Wh + WCHUNK;         // [104][WHP]

    const float beta1 = fminf(fmaxf(__ldg(pbeta1), 0.1f), 0.9f);
    const float beta2 = fminf(fmaxf(__ldg(pbeta2), 0.1f), 0.9f);
    const float thr1  = fmaxf(__ldg(pthr1), 0.1f);

    const int tid = threadIdx.x;

    // ---------------- phase 1: simulate 32 pairs x 512 h (R8 numerics) ------
    {
        const int q   = tid >> 3;   // pair slot 0..31
        const int sub = tid & 7;    // h-eighth
        int pp = blockIdx.x * NP + q;
        if (pp >= NPAIR) pp = 0;
        const int a = pp / PDIM;
        const int b = pp - a * PDIM;
        const float4* p1  = reinterpret_cast<const float4*>(g_P + a * HIDDEN);
        const float4* p2  = reinterpret_cast<const float4*>(g_P + (PDIM + b) * HIDDEN);
        const float4* b14 = reinterpret_cast<const float4*>(b1);

        const ull bt1 = dup_f32(beta1);
        const ull bt2 = dup_f32(beta2);
        const ull nt2 = dup_f32(-thr1);

        float4 n1 = __ldg(p1 + sub), n2 = __ldg(p2 + sub), nb = __ldg(b14 + sub);

#pragma unroll 1
        for (int o = 0; o < 16; o++) {
            const float4 v1 = n1, v2 = n2, vb = nb;
            if (o < 15) {
                const int h4n = sub + 8 * (o + 1);
                n1 = __ldg(p1 + h4n);
                n2 = __ldg(p2 + h4n);
                nb = __ldg(b14 + h4n);
            }
            ull c01 = add2(add2(pack2(v1.x, v1.y), pack2(v2.x, v2.y)),
                           pack2(vb.x, vb.y));
            ull c23 = add2(add2(pack2(v1.z, v1.w), pack2(v2.z, v2.w)),
                           pack2(vb.z, vb.w));

            ull m01 = 0, m23 = 0, S01 = 0, S23 = 0, sp01 = 0, sp23 = 0;
#pragma unroll
            for (int t = 0; t < NSTEPS; t++) {
                m01 = fma2v(sp01, nt2, fma2v(bt1, m01, c01));
                m23 = fma2v(sp23, nt2, fma2v(bt1, m23, c23));
                float a0, a1, a2, a3;
                unpack2(m01, a0, a1);
                unpack2(m23, a2, a3);
                sp01 = pack2(fsetgt(a0, thr1), fsetgt(a1, thr1));
                sp23 = pack2(fsetgt(a2, thr1), fsetgt(a3, thr1));
                S01 = fma2v(bt2, S01, sp01);
                S23 = fma2v(bt2, S23, sp23);
            }
            float s0, s1, s2, s3;
            unpack2(S01, s0, s1);
            unpack2(S23, s2, s3);
            u32 h0 = bfpack(s1, s0);
            u32 l0 = bfpack(s1 - bfhi(h0), s0 - bflo(h0));
            u32 h1 = bfpack(s3, s2);
            u32 l1 = bfpack(s3 - bfhi(h1), s2 - bflo(h1));
            const int h4 = sub + 8 * o;
            *reinterpret_cast<ull*>(Sh + q * SHP + 2 * h4) =
                (ull)h0 | ((ull)h1 << 32);
            *reinterpret_cast<ull*>(Sl + q * SHP + 2 * h4) =
                (ull)l0 | ((ull)l1 << 32);
        }
    }

    // ---------------- phase 2: tensor GEMM (3xBF16 split) -------------------
    const int warp = tid >> 5;
    const int lane = tid & 31;
    const int wm = warp & 1;    // m16-tile (2 tiles cover 32 pairs)
    const int wn = warp >> 1;   // 4 n-groups; nt = wn + 4*j (nt < 13)
    const int g  = lane >> 2;
    const int t  = lane & 3;

    float acc[4][4];
#pragma unroll
    for (int j = 0; j < 4; j++)
#pragma unroll
        for (int e = 0; e < 4; e++) acc[j][e] = 0.f;

    for (int kb = 0; kb < HIDDEN / KCH; kb++) {
        if (kb > 0) __syncthreads();   // previous chunk consumed
        // stage W2 chunk (bf16 hi/lo, rows >= 97 zero)
        for (int idx = tid; idx < 104 * (KCH / 2); idx += 256) {
            int p  = idx >> 5;
            int kp = idx & 31;
            float2 w = make_float2(0.f, 0.f);
            if (p < PDIM)
                w = *reinterpret_cast<const float2*>(
                        W2 + p * HIDDEN + kb * KCH + 2 * kp);
            u32 h = bfpack(w.y, w.x);
            u32 l = bfpack(w.y - bfhi(h), w.x - bflo(h));
            Wh[p * WHP + kp] = h;
            Wl[p * WHP + kp] = l;
        }
        __syncthreads();   // (also orders phase-1 Sh/Sl on kb==0)

#pragma unroll
        for (int ksl = 0; ksl < KCH / 16; ksl++) {
            const int kpg = (kb * (KCH / 16) + ksl) * 8 + t;
            const int kpl = ksl * 8 + t;
            u32 ah[4], al[4];
            const int prow = wm * 16 + g;
            ah[0] = Sh[prow * SHP + kpg];
            ah[1] = Sh[(prow + 8) * SHP + kpg];
            ah[2] = Sh[prow * SHP + kpg + 4];
            ah[3] = Sh[(prow + 8) * SHP + kpg + 4];
            al[0] = Sl[prow * SHP + kpg];
            al[1] = Sl[(prow + 8) * SHP + kpg];
            al[2] = Sl[prow * SHP + kpg + 4];
            al[3] = Sl[(prow + 8) * SHP + kpg + 4];
#pragma unroll
            for (int j = 0; j < 4; j++) {
                const int nt = wn + 4 * j;
                if (nt < 13) {
                    const int nrow = nt * 8 + g;
                    u32 bh0 = Wh[nrow * WHP + kpl];
                    u32 bh1 = Wh[nrow * WHP + kpl + 4];
                    u32 bl0 = Wl[nrow * WHP + kpl];
                    u32 bl1 = Wl[nrow * WHP + kpl + 4];
                    mma_bf16(acc[j], ah, bh0, bh1);  // hi*hi
                    mma_bf16(acc[j], al, bh0, bh1);  // lo*hi
                    mma_bf16(acc[j], ah, bl0, bl1);  // hi*lo
                }
            }
        }
    }

    // G = sum_{k=0..14} beta2^k via same recursion as mem2
    float G = 0.0f;
#pragma unroll
    for (int t2 = 0; t2 < NSTEPS; t2++) G = __fadd_rn(__fmul_rn(beta2, G), 1.0f);

    // store: c0:(g,2t) c1:(g,2t+1) c2:(g+8,2t) c3:(g+8,2t+1)
#pragma unroll
    for (int j = 0; j < 4; j++) {
        const int nt = wn + 4 * j;
        if (nt < 13) {
#pragma unroll
            for (int e = 0; e < 4; e++) {
                const int pp = blockIdx.x * NP + wm * 16 + g + (e >> 1) * 8;
                const int n = nt * 8 + 2 * t + (e & 1);
                if (pp < NPAIR && n < PDIM)
                    g_U[pp * UPITCH + n] = acc[j][e] + __ldg(b2 + n) * G;
            }
        }
    }
}

// ---------------------------------------------------------------------------
// Kernel C: out[b,:] = U[pair(b),:]. One warp per output row.
// ---------------------------------------------------------------------------
__global__ void __launch_bounds__(256) scatter_kernel(
    const int* __restrict__ x, float* __restrict__ out, int B)
{
    int warp = blockIdx.x * 8 + (threadIdx.x >> 5);
    int lane = threadIdx.x & 31;
    if (warp >= B) return;
    int x0 = __ldg(x + 2 * warp);
    int x1 = __ldg(x + 2 * warp + 1);
    const float* u = g_U + (size_t)(x0 * PDIM + x1) * UPITCH;
    float* o = out + (size_t)warp * PDIM;
#pragma unroll
    for (int j = 0; j < 3; j++) o[lane + 32 * j] = u[lane + 32 * j];
    if (lane == 0) o[96] = u[96];
}

// ---------------------------------------------------------------------------
extern "C" void kernel_launch(void* const* d_in, const int* in_sizes, int n_in,
                              void* d_out, int out_size)
{
    const int*   x     = (const int*)  d_in[0];
    const float* E     = (const float*)d_in[1];
    const float* W1    = (const float*)d_in[2];
    const float* b1    = (const float*)d_in[3];
    const float* W2    = (const float*)d_in[4];
    const float* b2    = (const float*)d_in[5];
    const float* beta1 = (const float*)d_in[6];
    const float* beta2 = (const float*)d_in[7];
    const float* thr1  = (const float*)d_in[8];
    // thr2 unused in forward (lif2 reset='none'; output is mem2).

    const int B = in_sizes[0] / 2;

    const int psmemB = (PVT * (HIDDEN / 4) + PJT * W1P4) * (int)sizeof(float4);
    cudaFuncSetAttribute(precompute_kernel,
                         cudaFuncAttributeMaxDynamicSharedMemorySize, psmemB);

    const int smemB = (2 * NP * SHP + 2 * WCHUNK) * (int)sizeof(u32); // 96512 B
    cudaFuncSetAttribute(pair_kernel, cudaFuncAttributeMaxDynamicSharedMemorySize, smemB);

    precompute_kernel<<<dim3(16, 13, 2), 128, psmemB>>>(E, W1);
    pair_kernel<<<(NPAIR + NP - 1) / NP, 256, smemB>>>(b1, W2, b2, beta1, beta2, thr1);
    scatter_kernel<<<(B + 7) / 8, 256>>>(x, (float*)d_out, B);
}